// round 15
// baseline (speedup 1.0000x reference)
#include <cuda_runtime.h>
#include <cstdint>
#include <cstddef>

// SBNet block-sparse 3x3 'same' conv — warp mma.sync TF32 implicit GEMM, v3.
// K-interleaved float2 fragment layouts + flat 72-iter loop with register
// double-buffering. 512 threads, cp.async zero-fill staging.

#define Hd   448
#define Wd   448
#define HW   (Hd*Wd)
#define Cin  64
#define Cout 64
#define BST  14

// B: Bt[64 co][584 floats]; col(tap,ci) = tap*64 + (ci>>3)*8 + (ci&3)*2 + ((ci>>2)&1)
// A: float2 As2[32 rows][292 pos]; row(ci) = (ci>>3)*4 + (ci&3), .x/.y = (ci>>2)&1
#define BT_STRIDE 584
#define BT2       292                      // float2 per B row
#define B_FLOATS  (Cout*BT_STRIDE)         // 37376
#define A_ROWPOS  292
#define A_FLOATS  (32*A_ROWPOS*2)          // 18688
#define A_OFF_F   B_FLOATS
#define SMEM_BYTES ((B_FLOATS + A_FLOATS)*4)  // 224256

#define NTHREADS 512

__device__ unsigned g_WB[B_FLOATS];
__device__ int      g_ctr;

static __device__ __forceinline__ uint32_t f2tf32(float f){
    uint32_t r; asm("cvt.rna.tf32.f32 %0, %1;" : "=r"(r) : "f"(f)); return r;
}
static __device__ __forceinline__ uint32_t smem_u32(const void* p){
    uint32_t a;
    asm("{ .reg .u64 t; cvta.to.shared.u64 t, %1; cvt.u32.u64 %0, t; }"
        : "=r"(a) : "l"(p));
    return a;
}
static __device__ __forceinline__ void mma_tf32(float* d, const uint32_t* a,
                                                const uint32_t* b){
    asm volatile(
        "mma.sync.aligned.m16n8k8.row.col.f32.tf32.tf32.f32 "
        "{%0,%1,%2,%3},{%4,%5,%6,%7},{%8,%9},{%0,%1,%2,%3};"
        : "+f"(d[0]), "+f"(d[1]), "+f"(d[2]), "+f"(d[3])
        : "r"(a[0]), "r"(a[1]), "r"(a[2]), "r"(a[3]), "r"(b[0]), "r"(b[1]));
}
static __device__ __forceinline__ void cp4(uint32_t dst, const void* src, int sz){
    asm volatile("cp.async.ca.shared.global [%0], [%1], 4, %2;"
                 :: "r"(dst), "l"(src), "r"(sz) : "memory");
}
#define CP_COMMIT() asm volatile("cp.async.commit_group;" ::: "memory")
#define CP_WAIT0()  asm volatile("cp.async.wait_group 0;" ::: "memory")

// w[co][ci][ky][kx] -> k-interleaved Bt (tf32). Also resets the work queue.
__global__ void repack_kernel(const float* __restrict__ w){
    int i = blockIdx.x * blockDim.x + threadIdx.x;
    if (i == 0) g_ctr = 0;
    if (i < Cout*Cin*9){
        int co  = i / (Cin*9);
        int rem = i - co*(Cin*9);
        int ci  = rem / 9;
        int tap = rem - ci*9;
        int col = tap*64 + ((ci>>3)<<3) + ((ci&3)<<1) + ((ci>>2)&1);
        g_WB[co*BT_STRIDE + col] = f2tf32(w[i]);
    }
}

// Load fragments for flat iteration it (tap = it>>3, ks = it&7) into FA/FB.
#define LDFRAG(it_, FA, FB) do{                                              \
    int tap_ = (it_) >> 3, ks_ = (it_) & 7;                                  \
    int ky_  = (tap_*43) >> 7;                                               \
    int kx_  = tap_ - ky_*3;                                                 \
    const float2* ap_ = Aw + ks_*(4*A_ROWPOS)                                \
                      + (apos0 + (ky_-1)*16 + (kx_-1));                      \
    FA[0][0] = ap_[0];  FA[0][1] = ap_[8];                                   \
    FA[1][0] = ap_[16]; FA[1][1] = ap_[24];                                  \
    const float2* bp_ = Bw + (it_)*4;                                        \
    FB[0] = bp_[0];      FB[1] = bp_[8*BT2];                                 \
    FB[2] = bp_[16*BT2]; FB[3] = bp_[24*BT2];                                \
}while(0)

#define MMA8(FA, FB) do{                                                     \
    uint32_t af_[2][4], bf_[4][2];                                           \
    _Pragma("unroll")                                                        \
    for (int l_ = 0; l_ < 2; l_++){                                          \
        af_[l_][0] = __float_as_uint(FA[l_][0].x);                           \
        af_[l_][1] = __float_as_uint(FA[l_][1].x);                           \
        af_[l_][2] = __float_as_uint(FA[l_][0].y);                           \
        af_[l_][3] = __float_as_uint(FA[l_][1].y);                           \
    }                                                                        \
    _Pragma("unroll")                                                        \
    for (int t_ = 0; t_ < 4; t_++){                                          \
        bf_[t_][0] = __float_as_uint(FB[t_].x);                              \
        bf_[t_][1] = __float_as_uint(FB[t_].y);                              \
    }                                                                        \
    _Pragma("unroll")                                                        \
    for (int l_ = 0; l_ < 2; l_++)                                           \
        _Pragma("unroll")                                                    \
        for (int t_ = 0; t_ < 4; t_++)                                       \
            mma_tf32(acc[l_][t_], af_[l_], bf_[t_]);                         \
}while(0)

__global__ void __launch_bounds__(NTHREADS, 1) conv_kernel(
    const float* __restrict__ x, const float* __restrict__ mask,
    const float* __restrict__ bias, float* __restrict__ out, int total_blocks)
{
    extern __shared__ float smem[];
    __shared__ float s_wmax[8];
    __shared__ int   s_bid;
    __shared__ float s_bias[Cout];

    const int tid  = threadIdx.x;
    const int wid  = tid >> 5;
    const int lane = tid & 31;
    const int gid  = lane >> 2;   // 0..7
    const int tig  = lane & 3;    // 0..3

    // ---- one-time: weights -> smem, zero A (incl. guards), bias ----
    {
        const uint4* src = reinterpret_cast<const uint4*>(g_WB);
        uint4* dst = reinterpret_cast<uint4*>(smem);
        for (int j = tid; j < B_FLOATS/4; j += NTHREADS) dst[j] = src[j];
        for (int j = tid; j < A_FLOATS; j += NTHREADS) smem[A_OFF_F + j] = 0.0f;
        if (tid < Cout) s_bias[tid] = bias[tid];
    }

    const int mg = wid >> 1;     // 0..7   (pos base mg*32)
    const int ng = wid & 1;      // 0..1   (co base ng*32)
    const int apos0 = 17 + mg*32 + gid;              // float2 pos index
    const float2* As2 = reinterpret_cast<const float2*>(smem + A_OFF_F);
    const float2* Aw  = As2 + tig*A_ROWPOS;
    const float2* Bw  = reinterpret_cast<const float2*>(smem)
                      + (ng*32 + gid)*BT2 + tig;

    // staging identity: 2 halves of 512 threads cover pos 0..255 x ci-slabs
    const int sp    = tid & 255;
    const int shalf = tid >> 8;            // ci slab: 0 -> 0..31, 1 -> 32..63
    const int sr = sp >> 4, sc = sp & 15;
    const uint32_t aBase = smem_u32(smem + A_OFF_F);

    for (;;){
        if (tid == 0) s_bid = atomicAdd(&g_ctr, 1);
        __syncthreads();
        const int bid = s_bid;
        if (bid >= total_blocks) break;

        const int n  = bid >> 10;
        const int by = (bid >> 5) & 31;
        const int bx = bid & 31;
        const int h0 = by*BST, w0 = bx*BST;

        // ---- activity: max(mask) over 16x16 window at (h0-1, w0-1) ----
        if (tid < 256){
            int gy = h0 - 1 + sr, gx = w0 - 1 + sc;
            float mv = -1e30f;
            if ((unsigned)gy < Hd && (unsigned)gx < Wd)
                mv = mask[(size_t)n*HW + (size_t)gy*Wd + gx];
            #pragma unroll
            for (int o = 16; o; o >>= 1)
                mv = fmaxf(mv, __shfl_xor_sync(0xffffffffu, mv, o));
            if (lane == 0) s_wmax[wid] = mv;
        }
        __syncthreads();
        float bm = s_wmax[0];
        #pragma unroll
        for (int i = 1; i < 8; i++) bm = fmaxf(bm, s_wmax[i]);

        if (!(bm > 0.5f)){
            for (int i = tid; i < Cout*BST; i += NTHREADS){
                int co = i / BST, r = i - co*BST;
                float2* p = reinterpret_cast<float2*>(
                    out + ((size_t)(n*Cout + co)*Hd + (h0 + r))*Wd + w0);
                #pragma unroll
                for (int j = 0; j < 7; j++) p[j] = make_float2(0.f, 0.f);
            }
            continue;
        }

        // ---- stage A via cp.async into k-interleaved layout ----
        {
            const int gy = h0 - 1 + sr, gx = w0 - 1 + sc;
            const bool ib = ((unsigned)gy < Hd) && ((unsigned)gx < Wd);
            const float* gp = ib
                ? (x + (size_t)n*Cin*HW + (size_t)(shalf*32)*HW + (size_t)gy*Wd + gx)
                : x;
            const int sz = ib ? 4 : 0;
            #pragma unroll
            for (int c = 0; c < 32; c++){
                int ci  = shalf*32 + c;
                int row = ((ci>>3)<<2) + (ci&3);
                int hi  = (ci>>2)&1;
                uint32_t dst = aBase + (uint32_t)((row*A_ROWPOS + 17 + sp)*8 + hi*4);
                cp4(dst, gp + (size_t)c*HW, sz);
            }
            CP_COMMIT();
            CP_WAIT0();
        }
        __syncthreads();

        // ---- mma: flat 72 iters, double-buffered fragments ----
        float acc[2][4][4];
        #pragma unroll
        for (int l = 0; l < 2; l++)
            #pragma unroll
            for (int t = 0; t < 4; t++)
                #pragma unroll
                for (int e = 0; e < 4; e++) acc[l][t][e] = 0.0f;

        {
            float2 fa0[2][2], fb0[4], fa1[2][2], fb1[4];
            LDFRAG(0, fa0, fb0);
            #pragma unroll 2
            for (int it = 0; it < 72; it += 2){
                LDFRAG(it+1, fa1, fb1);
                MMA8(fa0, fb0);
                if (it + 2 < 72) LDFRAG(it+2, fa0, fb0);
                MMA8(fa1, fb1);
            }
        }

        // ---- epilogue: direct STG. mt = mg*2+l is the output row index. ----
        #pragma unroll
        for (int l = 0; l < 2; l++){
            const int mt = mg*2 + l;
            if (mt < 1 || mt > 14) continue;          // uniform per warp
            float* orow = out + (size_t)n*Cout*HW
                        + (size_t)(h0 + mt - 1)*Wd + (w0 - 1);
            const int c0 = gid, c1 = gid + 8;
            const bool v0 = (c0 >= 1);
            const bool v1 = (c1 <= 14);
            #pragma unroll
            for (int t = 0; t < 4; t++){
                const int co = ng*32 + t*8 + 2*tig;
                const float bv0 = s_bias[co], bv1 = s_bias[co+1];
                if (v0){
                    orow[(size_t)co*HW + c0]     = acc[l][t][0] + bv0;
                    orow[(size_t)(co+1)*HW + c0] = acc[l][t][1] + bv1;
                }
                if (v1){
                    orow[(size_t)co*HW + c1]     = acc[l][t][2] + bv0;
                    orow[(size_t)(co+1)*HW + c1] = acc[l][t][3] + bv1;
                }
            }
        }
    }
}

extern "C" void kernel_launch(void* const* d_in, const int* in_sizes, int n_in,
                              void* d_out, int out_size) {
    const float* x    = (const float*)d_in[0];
    const float* mask = (const float*)d_in[1];
    const float* w    = (const float*)d_in[2];
    const float* bias = (const float*)d_in[3];
    float* out = (float*)d_out;

    const int N = in_sizes[0] / (Cin*HW);
    const int total_blocks = N * 32 * 32;

    cudaFuncSetAttribute(conv_kernel,
                         cudaFuncAttributeMaxDynamicSharedMemorySize, SMEM_BYTES);

    repack_kernel<<<(Cout*Cin*9 + 255)/256, 256>>>(w);
    conv_kernel<<<152, NTHREADS, SMEM_BYTES>>>(x, mask, bias, out, total_blocks);
}